// round 1
// baseline (speedup 1.0000x reference)
#include <cuda_runtime.h>

#define D 128
#define MAXN 50000
#define MAXE 600000
#define EPSV 1e-5f

// ---------------- scratch (no allocation allowed -> __device__ globals) ----
__device__ float g_deg[MAXN];
__device__ float g_dis[MAXN];
__device__ float g_bufH[(size_t)MAXN * D];   // h = x @ W
__device__ float g_bufA[(size_t)MAXN * D];   // aggregation target
__device__ float g_bufB[(size_t)MAXN * D];   // relu output
__device__ float g_sum[D];
__device__ float g_sumsq[D];

__device__ __forceinline__ void red_add_v4(float* addr, float4 v) {
    asm volatile("red.global.add.v4.f32 [%0], {%1, %2, %3, %4};"
                 :: "l"(addr), "f"(v.x), "f"(v.y), "f"(v.z), "f"(v.w)
                 : "memory");
}

// ---------------- degree / init ------------------------------------------
__global__ void k_init(int n) {
    int i = blockIdx.x * blockDim.x + threadIdx.x;
    if (i < n) g_deg[i] = 1.0f;                 // +1 self loop
    if (i < D) { g_sum[i] = 0.f; g_sumsq[i] = 0.f; }
}

__global__ void k_deg(const int* __restrict__ cols, int e) {
    int i = blockIdx.x * blockDim.x + threadIdx.x;
    if (i < e) atomicAdd(&g_deg[cols[i]], 1.0f);
}

__global__ void k_dis(int n) {
    int i = blockIdx.x * blockDim.x + threadIdx.x;
    if (i < n) g_dis[i] = rsqrtf(g_deg[i]);
}

// ---------------- GEMM: C = A @ W, C2 = C * dis^2 (self-loop init) -------
// block 256 threads, tile 128 rows x 64 cols, per-thread 4x8.
#define TBR 128
#define TBC 64
#define KC  16

__global__ void __launch_bounds__(256) k_gemm(const float* __restrict__ A,
                                              const float* __restrict__ W,
                                              float* __restrict__ C,
                                              float* __restrict__ C2,
                                              int n) {
    __shared__ float Ws[D][TBC];         // 32 KB
    __shared__ float As[KC][TBR + 4];    // ~8.3 KB (transposed A chunk)

    int tid = threadIdx.x;
    int c0 = blockIdx.y * TBC;
    int r0 = blockIdx.x * TBR;

    // Load W slab [128][64]: 8192 floats, 32 per thread (8 x float4)
    #pragma unroll
    for (int j = 0; j < 8; ++j) {
        int k  = (tid >> 4) + 16 * j;
        int c4 = tid & 15;
        float4 w = *(const float4*)(W + (size_t)k * D + c0 + c4 * 4);
        *(float4*)&Ws[k][c4 * 4] = w;
    }

    int tx = tid & 7;    // 8 col groups  -> cols tx*8 .. +7
    int ty = tid >> 3;   // 32 row groups -> rows ty*4 .. +3
    float acc[4][8];
    #pragma unroll
    for (int i = 0; i < 4; ++i)
        #pragma unroll
        for (int j = 0; j < 8; ++j) acc[i][j] = 0.f;

    for (int kc = 0; kc < D; kc += KC) {
        __syncthreads();
        // stage transposed A chunk: 128 rows x 16 k
        #pragma unroll
        for (int j = 0; j < 2; ++j) {
            int k4 = tid & 3;
            int r  = (tid >> 2) + 64 * j;
            int rg = r0 + r; if (rg >= n) rg = n - 1;
            float4 v = *(const float4*)(A + (size_t)rg * D + kc + k4 * 4);
            As[k4 * 4 + 0][r] = v.x;
            As[k4 * 4 + 1][r] = v.y;
            As[k4 * 4 + 2][r] = v.z;
            As[k4 * 4 + 3][r] = v.w;
        }
        __syncthreads();
        #pragma unroll
        for (int k = 0; k < KC; ++k) {
            float a[4], w[8];
            *(float4*)a       = *(const float4*)&As[k][ty * 4];
            *(float4*)w       = *(const float4*)&Ws[kc + k][tx * 8];
            *(float4*)(w + 4) = *(const float4*)&Ws[kc + k][tx * 8 + 4];
            #pragma unroll
            for (int i = 0; i < 4; ++i)
                #pragma unroll
                for (int j = 0; j < 8; ++j)
                    acc[i][j] = fmaf(a[i], w[j], acc[i][j]);
        }
    }

    // epilogue: write h and self-loop-scaled agg init
    #pragma unroll
    for (int i = 0; i < 4; ++i) {
        int rg = r0 + ty * 4 + i;
        if (rg < n) {
            float ds = g_dis[rg];
            float s  = ds * ds;
            float* cp  = C  + (size_t)rg * D + c0 + tx * 8;
            float* cp2 = C2 + (size_t)rg * D + c0 + tx * 8;
            float4 v0 = *(float4*)&acc[i][0];
            float4 v1 = *(float4*)&acc[i][4];
            *(float4*)cp       = v0;
            *(float4*)(cp + 4) = v1;
            float4 u0 = make_float4(v0.x * s, v0.y * s, v0.z * s, v0.w * s);
            float4 u1 = make_float4(v1.x * s, v1.y * s, v1.z * s, v1.w * s);
            *(float4*)cp2       = u0;
            *(float4*)(cp2 + 4) = u1;
        }
    }
}

// ---------------- edge propagation: one edge per warp --------------------
__global__ void __launch_bounds__(256) k_edge(const int* __restrict__ rows,
                                              const int* __restrict__ cols,
                                              const float* __restrict__ h,
                                              float* __restrict__ agg, int e) {
    int gw   = (blockIdx.x * blockDim.x + threadIdx.x) >> 5;
    int lane = threadIdx.x & 31;
    if (gw >= e) return;
    int r = rows[gw];
    int c = cols[gw];
    float norm = g_dis[r] * g_dis[c];
    float4 v = *(const float4*)(h + (size_t)r * D + lane * 4);
    v.x *= norm; v.y *= norm; v.z *= norm; v.w *= norm;
    red_add_v4(agg + (size_t)c * D + lane * 4, v);
}

// ---------------- bias + relu (+ optional BN stats) ----------------------
__global__ void __launch_bounds__(128) k_bias_relu(const float* __restrict__ in,
                                                   const float* __restrict__ b,
                                                   float* __restrict__ out,
                                                   int n, int do_stats) {
    int d = threadIdx.x;           // 128 threads = 1 row per iteration
    float bd = b[d];
    float s = 0.f, ss = 0.f;
    for (int r = blockIdx.x; r < n; r += gridDim.x) {
        float v = in[(size_t)r * D + d] + bd;
        v = fmaxf(v, 0.f);
        out[(size_t)r * D + d] = v;
        s += v; ss += v * v;
    }
    if (do_stats) {
        atomicAdd(&g_sum[d], s);
        atomicAdd(&g_sumsq[d], ss);
    }
}

// ---------------- BatchNorm apply ----------------------------------------
__global__ void k_bn(const float* __restrict__ h,
                     const float* __restrict__ gamma,
                     const float* __restrict__ beta,
                     float* __restrict__ out, int n) {
    int idx = blockIdx.x * blockDim.x + threadIdx.x;    // float4 index
    int total = n * (D / 4);
    if (idx >= total) return;
    int d0 = (idx & 31) * 4;
    float invN = 1.0f / (float)n;
    float4 v = ((const float4*)h)[idx];
    float vv[4] = {v.x, v.y, v.z, v.w};
    float res[4];
    #pragma unroll
    for (int s = 0; s < 4; ++s) {
        int d = d0 + s;
        float m   = g_sum[d] * invN;
        float var = g_sumsq[d] * invN - m * m;
        float inv = rsqrtf(var + EPSV);
        res[s] = gamma[d] * (vv[s] - m) * inv + beta[d];
    }
    ((float4*)out)[idx] = make_float4(res[0], res[1], res[2], res[3]);
}

// ---------------- launch --------------------------------------------------
extern "C" void kernel_launch(void* const* d_in, const int* in_sizes, int n_in,
                              void* d_out, int out_size) {
    const float* x     = (const float*)d_in[0];
    const int*   ei    = (const int*)d_in[1];
    const float* W1    = (const float*)d_in[2];
    const float* b1    = (const float*)d_in[3];
    const float* W2    = (const float*)d_in[4];
    const float* b2    = (const float*)d_in[5];
    const float* gamma = (const float*)d_in[6];
    const float* beta  = (const float*)d_in[7];
    float* out = (float*)d_out;

    int n = in_sizes[0] / D;
    int e = in_sizes[1] / 2;
    const int* rows = ei;
    const int* cols = ei + e;

    float *bufH, *bufA, *bufB;
    cudaGetSymbolAddress((void**)&bufH, g_bufH);
    cudaGetSymbolAddress((void**)&bufA, g_bufA);
    cudaGetSymbolAddress((void**)&bufB, g_bufB);

    int tb = 256;
    int nb_n  = (n + tb - 1) / tb;
    int nb_e  = (e + tb - 1) / tb;
    int nb_ew = (e * 32 + tb - 1) / tb;           // one edge per warp
    int nb_f4 = (n * (D / 4) + tb - 1) / tb;
    dim3 gemm_grid((n + TBR - 1) / TBR, D / TBC);

    k_init<<<nb_n, tb>>>(n);
    k_deg<<<nb_e, tb>>>(cols, e);
    k_dis<<<nb_n, tb>>>(n);

    // layer 1
    k_gemm<<<gemm_grid, 256>>>(x, W1, bufH, bufA, n);
    k_edge<<<nb_ew, tb>>>(rows, cols, bufH, bufA, e);
    k_bias_relu<<<512, 128>>>(bufA, b1, bufB, n, 0);

    // layer 2
    k_gemm<<<gemm_grid, 256>>>(bufB, W2, bufH, bufA, n);
    k_edge<<<nb_ew, tb>>>(rows, cols, bufH, bufA, e);
    k_bias_relu<<<512, 128>>>(bufA, b2, bufB, n, 1);

    // batchnorm
    k_bn<<<nb_f4, tb>>>(bufB, gamma, beta, out, n);
}

// round 2
// speedup vs baseline: 1.2978x; 1.2978x over previous
#include <cuda_runtime.h>

#define D 128
#define MAXN 50000
#define MAXE 600000
#define EPSV 1e-5f

typedef unsigned long long ull;

// ---------------- scratch ----------------
__device__ int   g_cnt[MAXN];
__device__ int   g_start[MAXN];
__device__ int   g_bsum[256];
__device__ float g_dis[MAXN];
__device__ int   g_srow[MAXE];
__device__ float g_bufH[(size_t)MAXN * D];
__device__ float g_bufB[(size_t)MAXN * D];
__device__ float g_sum[D];
__device__ float g_sumsq[D];

#define FMA2(d, a, b, c) \
    asm("fma.rn.f32x2 %0, %1, %2, %3;" : "=l"(d) : "l"(a), "l"(b), "l"(c))

__device__ __forceinline__ ull dup2(float x) {
    unsigned int u = __float_as_uint(x);
    return ((ull)u << 32) | (ull)u;
}

// ---------------- init / degree ----------------
__global__ void k_zero(int n) {
    int i = blockIdx.x * blockDim.x + threadIdx.x;
    if (i < n) g_cnt[i] = 0;
    if (i < D) { g_sum[i] = 0.f; g_sumsq[i] = 0.f; }
}

__global__ void k_deg(const int* __restrict__ cols, int e) {
    int i = blockIdx.x * blockDim.x + threadIdx.x;
    if (i < e) atomicAdd(&g_cnt[cols[i]], 1);
}

// ---------------- 2-level exclusive scan over g_cnt -> g_start ----------
__global__ void k_scan1(int n) {
    __shared__ int sh[256];
    int tid = threadIdx.x;
    int i = blockIdx.x * 256 + tid;
    int v = (i < n) ? g_cnt[i] : 0;
    sh[tid] = v;
    __syncthreads();
    #pragma unroll
    for (int off = 1; off < 256; off <<= 1) {
        int t = (tid >= off) ? sh[tid - off] : 0;
        __syncthreads();
        sh[tid] += t;
        __syncthreads();
    }
    if (i < n) g_start[i] = sh[tid] - v;             // exclusive
    if (tid == 255) g_bsum[blockIdx.x] = sh[255];
}

__global__ void k_scan2(int nb) {
    if (threadIdx.x == 0) {
        int run = 0;
        for (int b = 0; b < nb; ++b) {
            int t = g_bsum[b];
            g_bsum[b] = run;
            run += t;
        }
    }
}

__global__ void k_scan3(int n) {
    int i = blockIdx.x * blockDim.x + threadIdx.x;
    if (i < n) {
        g_start[i] += g_bsum[i >> 8];
        g_dis[i] = rsqrtf((float)g_cnt[i] + 1.0f);   // +1 self loop
        g_cnt[i] = 0;                                // reuse as scatter cursor
    }
}

__global__ void k_scatter(const int* __restrict__ rows,
                          const int* __restrict__ cols, int e) {
    int i = blockIdx.x * blockDim.x + threadIdx.x;
    if (i < e) {
        int c = cols[i];
        int p = g_start[c] + atomicAdd(&g_cnt[c], 1);
        g_srow[p] = rows[i];
    }
}

// ---------------- GEMM: C = A @ W  (f32x2 packed FMA) -------------------
#define TBR 128
#define TBC 64
#define KC  8

__global__ void __launch_bounds__(256) k_gemm(const float* __restrict__ A,
                                              const float* __restrict__ W,
                                              float* __restrict__ C, int n) {
    __shared__ __align__(16) float Ws[D][TBC];          // 32 KB
    __shared__ __align__(16) ull   As2[KC][TBR + 2];    // 8.3 KB, dup'd A
    int tid = threadIdx.x;
    int c0 = blockIdx.y * TBC;
    int r0 = blockIdx.x * TBR;

    // load W slab [128][64]
    #pragma unroll
    for (int j = 0; j < 8; ++j) {
        int k  = (tid >> 4) + 16 * j;
        int c4 = tid & 15;
        *(float4*)&Ws[k][c4 * 4] = *(const float4*)(W + (size_t)k * D + c0 + c4 * 4);
    }

    int tx = tid & 7;      // 8 col groups of 8
    int ty = tid >> 3;     // 32 row groups of 4
    ull acc[4][4];
    #pragma unroll
    for (int i = 0; i < 4; ++i)
        #pragma unroll
        for (int j = 0; j < 4; ++j) acc[i][j] = 0ull;

    int r  = tid >> 1;
    int kg = tid & 1;
    int rg = r0 + r; if (rg >= n) rg = n - 1;
    const float* Arow = A + (size_t)rg * D + kg * 4;

    for (int kc = 0; kc < D; kc += KC) {
        __syncthreads();
        float4 v = *(const float4*)(Arow + kc);
        As2[kg * 4 + 0][r] = dup2(v.x);
        As2[kg * 4 + 1][r] = dup2(v.y);
        As2[kg * 4 + 2][r] = dup2(v.z);
        As2[kg * 4 + 3][r] = dup2(v.w);
        __syncthreads();
        #pragma unroll
        for (int k = 0; k < KC; ++k) {
            ulonglong2 a01 = *(ulonglong2*)&As2[k][ty * 4];
            ulonglong2 a23 = *(ulonglong2*)&As2[k][ty * 4 + 2];
            ulonglong2 w01 = *(ulonglong2*)&Ws[kc + k][tx * 8];
            ulonglong2 w23 = *(ulonglong2*)&Ws[kc + k][tx * 8 + 4];
            ull av[4] = {a01.x, a01.y, a23.x, a23.y};
            ull wv[4] = {w01.x, w01.y, w23.x, w23.y};
            #pragma unroll
            for (int i = 0; i < 4; ++i)
                #pragma unroll
                for (int j = 0; j < 4; ++j)
                    FMA2(acc[i][j], av[i], wv[j], acc[i][j]);
        }
    }

    #pragma unroll
    for (int i = 0; i < 4; ++i) {
        int rr = r0 + ty * 4 + i;
        if (rr < n) {
            float2 p0 = *(float2*)&acc[i][0];
            float2 p1 = *(float2*)&acc[i][1];
            float2 p2 = *(float2*)&acc[i][2];
            float2 p3 = *(float2*)&acc[i][3];
            float* cp = C + (size_t)rr * D + c0 + tx * 8;
            *(float4*)cp       = make_float4(p0.x, p0.y, p1.x, p1.y);
            *(float4*)(cp + 4) = make_float4(p2.x, p2.y, p3.x, p3.y);
        }
    }
}

// -------- aggregation: warp per node, fused bias+ReLU (+BN stats) -------
__global__ void __launch_bounds__(256) k_agg(const float* __restrict__ h,
                                             const float* __restrict__ b,
                                             float* __restrict__ out,
                                             int n, int do_stats) {
    __shared__ float s_sum[D];
    __shared__ float s_sq[D];
    int tid  = threadIdx.x;
    int lane = tid & 31;
    int wid  = tid >> 5;
    if (do_stats) {
        if (tid < D) { s_sum[tid] = 0.f; s_sq[tid] = 0.f; }
        __syncthreads();
    }
    float4 b4 = *(const float4*)(b + lane * 4);

    for (int c = blockIdx.x * 8 + wid; c < n; c += gridDim.x * 8) {
        int s0  = g_start[c];
        int cnt = g_cnt[c];
        float4 acc = make_float4(0.f, 0.f, 0.f, 0.f);
        for (int j = s0; j < s0 + cnt; ++j) {
            int   rr = __ldg(&g_srow[j]);
            float dr = __ldg(&g_dis[rr]);
            float4 v = *(const float4*)(h + (size_t)rr * D + lane * 4);
            acc.x = fmaf(v.x, dr, acc.x);
            acc.y = fmaf(v.y, dr, acc.y);
            acc.z = fmaf(v.z, dr, acc.z);
            acc.w = fmaf(v.w, dr, acc.w);
        }
        float dc = g_dis[c];
        float sc = dc * dc;
        float4 hc = *(const float4*)(h + (size_t)c * D + lane * 4);
        float4 r4;
        r4.x = fmaxf(fmaf(acc.x, dc, fmaf(hc.x, sc, b4.x)), 0.f);
        r4.y = fmaxf(fmaf(acc.y, dc, fmaf(hc.y, sc, b4.y)), 0.f);
        r4.z = fmaxf(fmaf(acc.z, dc, fmaf(hc.z, sc, b4.z)), 0.f);
        r4.w = fmaxf(fmaf(acc.w, dc, fmaf(hc.w, sc, b4.w)), 0.f);
        *(float4*)(out + (size_t)c * D + lane * 4) = r4;
        if (do_stats) {
            int d0 = lane * 4;
            atomicAdd(&s_sum[d0 + 0], r4.x); atomicAdd(&s_sq[d0 + 0], r4.x * r4.x);
            atomicAdd(&s_sum[d0 + 1], r4.y); atomicAdd(&s_sq[d0 + 1], r4.y * r4.y);
            atomicAdd(&s_sum[d0 + 2], r4.z); atomicAdd(&s_sq[d0 + 2], r4.z * r4.z);
            atomicAdd(&s_sum[d0 + 3], r4.w); atomicAdd(&s_sq[d0 + 3], r4.w * r4.w);
        }
    }
    if (do_stats) {
        __syncthreads();
        if (tid < D) {
            atomicAdd(&g_sum[tid], s_sum[tid]);
            atomicAdd(&g_sumsq[tid], s_sq[tid]);
        }
    }
}

// ---------------- BatchNorm apply ----------------
__global__ void k_bn(const float* __restrict__ h,
                     const float* __restrict__ gamma,
                     const float* __restrict__ beta,
                     float* __restrict__ out, int n) {
    int idx = blockIdx.x * blockDim.x + threadIdx.x;
    int total = n * (D / 4);
    if (idx >= total) return;
    int d0 = (idx & 31) * 4;
    float invN = 1.0f / (float)n;
    float4 v = ((const float4*)h)[idx];
    float vv[4] = {v.x, v.y, v.z, v.w};
    float res[4];
    #pragma unroll
    for (int s = 0; s < 4; ++s) {
        int d = d0 + s;
        float m   = g_sum[d] * invN;
        float var = g_sumsq[d] * invN - m * m;
        float inv = rsqrtf(var + EPSV);
        res[s] = gamma[d] * (vv[s] - m) * inv + beta[d];
    }
    ((float4*)out)[idx] = make_float4(res[0], res[1], res[2], res[3]);
}

// ---------------- launch ----------------
extern "C" void kernel_launch(void* const* d_in, const int* in_sizes, int n_in,
                              void* d_out, int out_size) {
    const float* x     = (const float*)d_in[0];
    const int*   ei    = (const int*)d_in[1];
    const float* W1    = (const float*)d_in[2];
    const float* b1    = (const float*)d_in[3];
    const float* W2    = (const float*)d_in[4];
    const float* b2    = (const float*)d_in[5];
    const float* gamma = (const float*)d_in[6];
    const float* beta  = (const float*)d_in[7];
    float* out = (float*)d_out;

    int n = in_sizes[0] / D;
    int e = in_sizes[1] / 2;
    const int* rows = ei;
    const int* cols = ei + e;

    float *bufH, *bufB;
    cudaGetSymbolAddress((void**)&bufH, g_bufH);
    cudaGetSymbolAddress((void**)&bufB, g_bufB);

    int tb = 256;
    int nb_n  = (n + tb - 1) / tb;
    int nb_e  = (e + tb - 1) / tb;
    int nb_f4 = (n * (D / 4) + tb - 1) / tb;
    dim3 gemm_grid((n + TBR - 1) / TBR, D / TBC);
    int agg_grid = 2048;

    // CSR build
    k_zero<<<nb_n, tb>>>(n);
    k_deg<<<nb_e, tb>>>(cols, e);
    k_scan1<<<nb_n, 256>>>(n);
    k_scan2<<<1, 32>>>(nb_n);
    k_scan3<<<nb_n, tb>>>(n);
    k_scatter<<<nb_e, tb>>>(rows, cols, e);

    // layer 1
    k_gemm<<<gemm_grid, 256>>>(x, W1, bufH, n);
    k_agg<<<agg_grid, 256>>>(bufH, b1, bufB, n, 0);

    // layer 2
    k_gemm<<<gemm_grid, 256>>>(bufB, W2, bufH, n);
    k_agg<<<agg_grid, 256>>>(bufH, b2, bufB, n, 1);

    // batchnorm
    k_bn<<<nb_f4, tb>>>(bufB, gamma, beta, out, n);
}

// round 4
// speedup vs baseline: 1.3192x; 1.0164x over previous
#include <cuda_runtime.h>
#include <cuda_bf16.h>
#include <cstdint>

#define D 128
#define MAXN 50000
#define MAXE 600000
#define EPSV 1e-5f

typedef unsigned long long ull;

// ---------------- scratch ----------------
__device__ int   g_cnt[MAXN];
__device__ int   g_start[MAXN];
__device__ float g_dis[MAXN];
__device__ int   g_srow[MAXE];
__device__ float g_bufH[(size_t)MAXN * D];   // GEMM output (float)
__device__ float g_bufB[(size_t)MAXN * D];   // layer2 relu output (float)
__device__ __nv_bfloat16 g_Ahi[(size_t)MAXN * D];
__device__ __nv_bfloat16 g_Alo[(size_t)MAXN * D];
__device__ __nv_bfloat16 g_WThi1[D * D];
__device__ __nv_bfloat16 g_WTlo1[D * D];
__device__ __nv_bfloat16 g_WThi2[D * D];
__device__ __nv_bfloat16 g_WTlo2[D * D];
__device__ float g_sum[D];
__device__ float g_sumsq[D];

// ---------------- helpers ----------------
__device__ __forceinline__ uint32_t smem_u32(const void* p) {
    uint32_t a;
    asm("{ .reg .u64 t; cvta.to.shared.u64 t, %1; cvt.u32.u64 %0, t; }"
        : "=r"(a) : "l"(p));
    return a;
}

#define LDSM4(r0, r1, r2, r3, addr) \
    asm volatile("ldmatrix.sync.aligned.m8n8.x4.shared.b16 {%0,%1,%2,%3}, [%4];" \
        : "=r"(r0), "=r"(r1), "=r"(r2), "=r"(r3) : "r"(addr))

#define MMA_BF16(d, a, b) \
    asm volatile("mma.sync.aligned.m16n8k16.row.col.f32.bf16.bf16.f32 " \
        "{%0,%1,%2,%3}, {%4,%5,%6,%7}, {%8,%9}, {%0,%1,%2,%3};" \
        : "+f"((d)[0]), "+f"((d)[1]), "+f"((d)[2]), "+f"((d)[3]) \
        : "r"((a)[0]), "r"((a)[1]), "r"((a)[2]), "r"((a)[3]), \
          "r"((b)[0]), "r"((b)[1]))

__device__ __forceinline__ void split_bf16(float v, __nv_bfloat16& h, __nv_bfloat16& l) {
    h = __float2bfloat16_rn(v);
    l = __float2bfloat16_rn(v - __bfloat162float(h));
}

// ---------------- init / degree / CSR ----------------
__global__ void k_zero(int n) {
    int i = blockIdx.x * blockDim.x + threadIdx.x;
    if (i < n) g_cnt[i] = 0;
}

__global__ void k_deg(const int* __restrict__ cols, int e) {
    int i = blockIdx.x * blockDim.x + threadIdx.x;
    if (i < e) atomicAdd(&g_cnt[cols[i]], 1);
}

// single-block scan: g_cnt -> g_start (exclusive), g_dis, reset g_cnt, zero stats
__global__ void __launch_bounds__(1024) k_scanall(int n) {
    __shared__ int sh[1024];
    int t = threadIdx.x;
    int chunk = (n + 1023) >> 10;
    int lo = t * chunk;
    int hi = min(lo + chunk, n);
    int s = 0;
    for (int i = lo; i < hi; ++i) s += g_cnt[i];
    sh[t] = s;
    __syncthreads();
    #pragma unroll
    for (int off = 1; off < 1024; off <<= 1) {
        int v = (t >= off) ? sh[t - off] : 0;
        __syncthreads();
        sh[t] += v;
        __syncthreads();
    }
    int run = (t == 0) ? 0 : sh[t - 1];
    for (int i = lo; i < hi; ++i) {
        int c = g_cnt[i];
        g_start[i] = run;
        run += c;
        g_dis[i] = rsqrtf((float)c + 1.0f);
        g_cnt[i] = 0;
    }
    if (t < D) { g_sum[t] = 0.f; g_sumsq[t] = 0.f; }
}

__global__ void k_scatter(const int* __restrict__ rows,
                          const int* __restrict__ cols, int e) {
    int i = blockIdx.x * blockDim.x + threadIdx.x;
    if (i < e) {
        int c = cols[i];
        int p = g_start[c] + atomicAdd(&g_cnt[c], 1);
        g_srow[p] = rows[i];
    }
}

// ---------------- prep: W transpose + bf16 hi/lo split -------------------
__global__ void k_prepW(const float* __restrict__ W,
                        __nv_bfloat16* __restrict__ hi,
                        __nv_bfloat16* __restrict__ lo) {
    int idx = blockIdx.x * blockDim.x + threadIdx.x;   // 16384
    int k = idx >> 7, nn = idx & 127;
    __nv_bfloat16 h, l;
    split_bf16(W[idx], h, l);
    hi[nn * D + k] = h;
    lo[nn * D + k] = l;
}

// x -> bf16 hi/lo
__global__ void k_prepX(const float* __restrict__ x,
                        __nv_bfloat16* __restrict__ hi,
                        __nv_bfloat16* __restrict__ lo, int total4) {
    int i = blockIdx.x * blockDim.x + threadIdx.x;
    if (i >= total4) return;
    float4 v = ((const float4*)x)[i];
    __nv_bfloat16 h[4], l[4];
    split_bf16(v.x, h[0], l[0]);
    split_bf16(v.y, h[1], l[1]);
    split_bf16(v.z, h[2], l[2]);
    split_bf16(v.w, h[3], l[3]);
    *(uint2*)(hi + (size_t)i * 4) = *(uint2*)h;
    *(uint2*)(lo + (size_t)i * 4) = *(uint2*)l;
}

// ---------------- bf16 mma.sync GEMM with 3-term compensation ------------
// C[128 x 128] per block. 8 warps: warp tile 32 rows x 64 cols.
#define WSTRIDE 136   // bf16 units; 272B rows -> 4-bank steps, conflict-free LDSM
#define ASTRIDE 56    // bf16 units; 112B rows -> 28-bank steps, conflict-free
#define SM_WHI 0
#define SM_WLO 34816
#define SM_AHI 69632
#define SM_ALO 83968
#define GEMM_SMEM 98304

__global__ void __launch_bounds__(256, 1)
k_gemm_mma(const __nv_bfloat16* __restrict__ Ahi,
           const __nv_bfloat16* __restrict__ Alo,
           const __nv_bfloat16* __restrict__ Whi,
           const __nv_bfloat16* __restrict__ Wlo,
           float* __restrict__ C, int n) {
    extern __shared__ __align__(16) char sm[];
    uint32_t sb = smem_u32(sm);
    int t = threadIdx.x, lane = t & 31, wid = t >> 5;
    int r0 = blockIdx.x * 128;
    int wm = (wid >> 1) * 32;       // warp row offset
    int wn = (wid & 1) * 64;        // warp col offset

    // stage W hi/lo [128 n][128 k] -> padded smem
    {
        int row = t >> 1, half = t & 1;
        const uint4* gh = (const uint4*)(Whi + row * D + half * 64);
        const uint4* gl = (const uint4*)(Wlo + row * D + half * 64);
        uint4* shh = (uint4*)(sm + SM_WHI + (row * WSTRIDE + half * 64) * 2);
        uint4* shl = (uint4*)(sm + SM_WLO + (row * WSTRIDE + half * 64) * 2);
        #pragma unroll
        for (int j = 0; j < 8; ++j) { shh[j] = gh[j]; shl[j] = gl[j]; }
    }

    // ldmatrix lane address components
    int qa = lane >> 3, la = lane & 7;
    int ra = (qa & 1) * 8 + la;          // A row within m16 tile
    int ka = (qa >> 1) * 8;              // A k-half offset
    int nb = (qa >> 1) * 8 + la;         // B n within pair (tile-relative, see below)
    int kb = (qa & 1) * 8;               // B k-half offset

    uint32_t aHiB = sb + SM_AHI + ((wm + ra) * ASTRIDE + ka) * 2;
    uint32_t aLoB = sb + SM_ALO + ((wm + ra) * ASTRIDE + ka) * 2;
    // B pair p covers n-tiles 2p,2p+1: row = wn + p*16 + nb
    uint32_t bHiB = sb + SM_WHI + ((wn + nb) * WSTRIDE + kb) * 2;
    uint32_t bLoB = sb + SM_WLO + ((wn + nb) * WSTRIDE + kb) * 2;

    float acc[2][8][4];
    #pragma unroll
    for (int mt = 0; mt < 2; ++mt)
        #pragma unroll
        for (int nt = 0; nt < 8; ++nt)
            #pragma unroll
            for (int q = 0; q < 4; ++q) acc[mt][nt][q] = 0.f;

    int arow = t >> 1, apart = t & 1;
    int arg = r0 + arow; if (arg >= n) arg = n - 1;
    const uint4* gAh = (const uint4*)(Ahi + (size_t)arg * D + apart * 16);
    const uint4* gAl = (const uint4*)(Alo + (size_t)arg * D + apart * 16);
    uint4* sAh = (uint4*)(sm + SM_AHI + (arow * ASTRIDE + apart * 16) * 2);
    uint4* sAl = (uint4*)(sm + SM_ALO + (arow * ASTRIDE + apart * 16) * 2);

    for (int kc = 0; kc < 4; ++kc) {
        __syncthreads();
        // stage A chunk [128][32] hi/lo  (global k offset = kc*32 + apart*16)
        sAh[0] = gAh[kc * 4 + 0]; sAh[1] = gAh[kc * 4 + 1];
        sAl[0] = gAl[kc * 4 + 0]; sAl[1] = gAl[kc * 4 + 1];
        __syncthreads();

        #pragma unroll
        for (int s = 0; s < 2; ++s) {
            uint32_t ah[2][4], al[2][4], bh[8][2], bl[8][2];
            #pragma unroll
            for (int mt = 0; mt < 2; ++mt) {
                uint32_t ao = (uint32_t)(mt * 16 * ASTRIDE * 2 + s * 32);
                LDSM4(ah[mt][0], ah[mt][1], ah[mt][2], ah[mt][3], aHiB + ao);
                LDSM4(al[mt][0], al[mt][1], al[mt][2], al[mt][3], aLoB + ao);
            }
            #pragma unroll
            for (int p = 0; p < 4; ++p) {
                uint32_t bo = (uint32_t)(p * 16 * WSTRIDE * 2 + (kc * 32 + s * 16) * 2);
                LDSM4(bh[2*p][0], bh[2*p][1], bh[2*p+1][0], bh[2*p+1][1], bHiB + bo);
                LDSM4(bl[2*p][0], bl[2*p][1], bl[2*p+1][0], bl[2*p+1][1], bLoB + bo);
            }
            #pragma unroll
            for (int mt = 0; mt < 2; ++mt)
                #pragma unroll
                for (int nt = 0; nt < 8; ++nt) {
                    MMA_BF16(acc[mt][nt], ah[mt], bh[nt]);
                    MMA_BF16(acc[mt][nt], al[mt], bh[nt]);
                    MMA_BF16(acc[mt][nt], ah[mt], bl[nt]);
                }
        }
    }

    // epilogue
    int tr = lane >> 2, tc = (lane & 3) * 2;
    #pragma unroll
    for (int mt = 0; mt < 2; ++mt)
        #pragma unroll
        for (int nt = 0; nt < 8; ++nt) {
            int row = r0 + wm + mt * 16 + tr;
            int col = wn + nt * 8 + tc;
            if (row < n)
                *(float2*)(C + (size_t)row * D + col) =
                    make_float2(acc[mt][nt][0], acc[mt][nt][1]);
            if (row + 8 < n)
                *(float2*)(C + (size_t)(row + 8) * D + col) =
                    make_float2(acc[mt][nt][2], acc[mt][nt][3]);
        }
}

// -------- aggregation: warp per node, fused bias+ReLU --------------------
// mode 0: write bf16 hi/lo (feeds next GEMM).  mode 1: write float + BN stats.
__global__ void __launch_bounds__(256) k_agg(const float* __restrict__ h,
                                             const float* __restrict__ b,
                                             float* __restrict__ outF,
                                             __nv_bfloat16* __restrict__ outHi,
                                             __nv_bfloat16* __restrict__ outLo,
                                             int n, int do_stats) {
    __shared__ float s_sum[D];
    __shared__ float s_sq[D];
    int tid  = threadIdx.x;
    int lane = tid & 31;
    int wid  = tid >> 5;
    if (do_stats) {
        if (tid < D) { s_sum[tid] = 0.f; s_sq[tid] = 0.f; }
        __syncthreads();
    }
    float4 b4 = *(const float4*)(b + lane * 4);

    for (int c = blockIdx.x * 8 + wid; c < n; c += gridDim.x * 8) {
        int s0  = g_start[c];
        int cnt = g_cnt[c];
        float4 acc = make_float4(0.f, 0.f, 0.f, 0.f);
        for (int j = s0; j < s0 + cnt; ++j) {
            int   rr = __ldg(&g_srow[j]);
            float dr = __ldg(&g_dis[rr]);
            float4 v = *(const float4*)(h + (size_t)rr * D + lane * 4);
            acc.x = fmaf(v.x, dr, acc.x);
            acc.y = fmaf(v.y, dr, acc.y);
            acc.z = fmaf(v.z, dr, acc.z);
            acc.w = fmaf(v.w, dr, acc.w);
        }
        float dc = g_dis[c];
        float sc = dc * dc;
        float4 hc = *(const float4*)(h + (size_t)c * D + lane * 4);
        float4 r4;
        r4.x = fmaxf(fmaf(acc.x, dc, fmaf(hc.x, sc, b4.x)), 0.f);
        r4.y = fmaxf(fmaf(acc.y, dc, fmaf(hc.y, sc, b4.y)), 0.f);
        r4.z = fmaxf(fmaf(acc.z, dc, fmaf(hc.z, sc, b4.z)), 0.f);
        r4.w = fmaxf(fmaf(acc.w, dc, fmaf(hc.w, sc, b4.w)), 0.f);
        if (do_stats) {
            *(float4*)(outF + (size_t)c * D + lane * 4) = r4;
            int d0 = lane * 4;
            atomicAdd(&s_sum[d0 + 0], r4.x); atomicAdd(&s_sq[d0 + 0], r4.x * r4.x);
            atomicAdd(&s_sum[d0 + 1], r4.y); atomicAdd(&s_sq[d0 + 1], r4.y * r4.y);
            atomicAdd(&s_sum[d0 + 2], r4.z); atomicAdd(&s_sq[d0 + 2], r4.z * r4.z);
            atomicAdd(&s_sum[d0 + 3], r4.w); atomicAdd(&s_sq[d0 + 3], r4.w * r4.w);
        } else {
            __nv_bfloat16 hh[4], ll[4];
            split_bf16(r4.x, hh[0], ll[0]);
            split_bf16(r4.y, hh[1], ll[1]);
            split_bf16(r4.z, hh[2], ll[2]);
            split_bf16(r4.w, hh[3], ll[3]);
            *(uint2*)(outHi + (size_t)c * D + lane * 4) = *(uint2*)hh;
            *(uint2*)(outLo + (size_t)c * D + lane * 4) = *(uint2*)ll;
        }
    }
    if (do_stats) {
        __syncthreads();
        if (tid < D) {
            atomicAdd(&g_sum[tid], s_sum[tid]);
            atomicAdd(&g_sumsq[tid], s_sq[tid]);
        }
    }
}

// ---------------- BatchNorm apply ----------------
__global__ void k_bn(const float* __restrict__ h,
                     const float* __restrict__ gamma,
                     const float* __restrict__ beta,
                     float* __restrict__ out, int n) {
    int idx = blockIdx.x * blockDim.x + threadIdx.x;
    int total = n * (D / 4);
    if (idx >= total) return;
    int d0 = (idx & 31) * 4;
    float invN = 1.0f / (float)n;
    float4 v = ((const float4*)h)[idx];
    float vv[4] = {v.x, v.y, v.z, v.w};
    float res[4];
    #pragma unroll
    for (int s = 0; s < 4; ++s) {
        int d = d0 + s;
        float m   = g_sum[d] * invN;
        float var = g_sumsq[d] * invN - m * m;
        float inv = rsqrtf(var + EPSV);
        res[s] = gamma[d] * (vv[s] - m) * inv + beta[d];
    }
    ((float4*)out)[idx] = make_float4(res[0], res[1], res[2], res[3]);
}

// ---------------- launch ----------------
extern "C" void kernel_launch(void* const* d_in, const int* in_sizes, int n_in,
                              void* d_out, int out_size) {
    const float* x     = (const float*)d_in[0];
    const int*   ei    = (const int*)d_in[1];
    const float* W1    = (const float*)d_in[2];
    const float* b1    = (const float*)d_in[3];
    const float* W2    = (const float*)d_in[4];
    const float* b2    = (const float*)d_in[5];
    const float* gamma = (const float*)d_in[6];
    const float* beta  = (const float*)d_in[7];
    float* out = (float*)d_out;

    int n = in_sizes[0] / D;
    int e = in_sizes[1] / 2;
    const int* rows = ei;
    const int* cols = ei + e;

    float *bufH, *bufB;
    __nv_bfloat16 *ahi, *alo, *wh1, *wl1, *wh2, *wl2;
    cudaGetSymbolAddress((void**)&bufH, g_bufH);
    cudaGetSymbolAddress((void**)&bufB, g_bufB);
    cudaGetSymbolAddress((void**)&ahi, g_Ahi);
    cudaGetSymbolAddress((void**)&alo, g_Alo);
    cudaGetSymbolAddress((void**)&wh1, g_WThi1);
    cudaGetSymbolAddress((void**)&wl1, g_WTlo1);
    cudaGetSymbolAddress((void**)&wh2, g_WThi2);
    cudaGetSymbolAddress((void**)&wl2, g_WTlo2);

    cudaFuncSetAttribute(k_gemm_mma, cudaFuncAttributeMaxDynamicSharedMemorySize,
                         GEMM_SMEM);

    int tb = 256;
    int nb_n  = (n + tb - 1) / tb;
    int nb_e  = (e + tb - 1) / tb;
    int nb_f4 = (n * (D / 4) + tb - 1) / tb;
    int gemm_grid = (n + 127) / 128;
    int agg_grid = 2048;

    // CSR build + splits
    k_zero<<<nb_n, tb>>>(n);
    k_deg<<<nb_e, tb>>>(cols, e);
    k_prepW<<<(D * D) / tb, tb>>>(W1, wh1, wl1);
    k_prepW<<<(D * D) / tb, tb>>>(W2, wh2, wl2);
    k_prepX<<<nb_f4, tb>>>(x, ahi, alo, n * (D / 4));
    k_scanall<<<1, 1024>>>(n);
    k_scatter<<<nb_e, tb>>>(rows, cols, e);

    // layer 1
    k_gemm_mma<<<gemm_grid, 256, GEMM_SMEM>>>(ahi, alo, wh1, wl1, bufH, n);
    k_agg<<<agg_grid, 256>>>(bufH, b1, nullptr, ahi, alo, n, 0);

    // layer 2
    k_gemm_mma<<<gemm_grid, 256, GEMM_SMEM>>>(ahi, alo, wh2, wl2, bufH, n);
    k_agg<<<agg_grid, 256>>>(bufH, b2, bufB, nullptr, nullptr, n, 1);

    // batchnorm
    k_bn<<<nb_f4, tb>>>(bufB, gamma, beta, out, n);
}

// round 5
// speedup vs baseline: 1.3312x; 1.0091x over previous
#include <cuda_runtime.h>
#include <cuda_bf16.h>
#include <cstdint>

#define D 128
#define MAXN 50000
#define MAXE 600000
#define EPSV 1e-5f

typedef unsigned long long ull;

// ---------------- scratch ----------------
__device__ int   g_cnt[MAXN];
__device__ int   g_start[MAXN];
__device__ float g_dis[MAXN];
__device__ int   g_srow[MAXE];
__device__ float g_bufH[(size_t)MAXN * D];   // GEMM output (float)
__device__ float g_bufB[(size_t)MAXN * D];   // layer2 relu output (float)
__device__ __nv_bfloat16 g_Ahi[(size_t)MAXN * D];
__device__ __nv_bfloat16 g_Alo[(size_t)MAXN * D];
__device__ __nv_bfloat16 g_WThi1[D * D];
__device__ __nv_bfloat16 g_WTlo1[D * D];
__device__ __nv_bfloat16 g_WThi2[D * D];
__device__ __nv_bfloat16 g_WTlo2[D * D];
__device__ float g_sum[D];
__device__ float g_sumsq[D];

// ---------------- helpers ----------------
__device__ __forceinline__ uint32_t smem_u32(const void* p) {
    uint32_t a;
    asm("{ .reg .u64 t; cvta.to.shared.u64 t, %1; cvt.u32.u64 %0, t; }"
        : "=r"(a) : "l"(p));
    return a;
}

#define LDSM4(r0, r1, r2, r3, addr) \
    asm volatile("ldmatrix.sync.aligned.m8n8.x4.shared.b16 {%0,%1,%2,%3}, [%4];" \
        : "=r"(r0), "=r"(r1), "=r"(r2), "=r"(r3) : "r"(addr))

#define MMA_BF16(d, a, b) \
    asm volatile("mma.sync.aligned.m16n8k16.row.col.f32.bf16.bf16.f32 " \
        "{%0,%1,%2,%3}, {%4,%5,%6,%7}, {%8,%9}, {%0,%1,%2,%3};" \
        : "+f"((d)[0]), "+f"((d)[1]), "+f"((d)[2]), "+f"((d)[3]) \
        : "r"((a)[0]), "r"((a)[1]), "r"((a)[2]), "r"((a)[3]), \
          "r"((b)[0]), "r"((b)[1]))

__device__ __forceinline__ void split_bf16(float v, __nv_bfloat16& h, __nv_bfloat16& l) {
    h = __float2bfloat16_rn(v);
    l = __float2bfloat16_rn(v - __bfloat162float(h));
}

// ---------------- merged prep: zero cnt + split W1/W2/x ------------------
__global__ void k_prep(const float* __restrict__ W1,
                       const float* __restrict__ W2,
                       const float* __restrict__ x,
                       int n, int total4) {
    int i = blockIdx.x * blockDim.x + threadIdx.x;
    if (i < n) g_cnt[i] = 0;
    if (i < D * D) {
        int k = i >> 7, nn = i & 127;
        __nv_bfloat16 h, l;
        split_bf16(W1[i], h, l);
        g_WThi1[nn * D + k] = h;
        g_WTlo1[nn * D + k] = l;
        split_bf16(W2[i], h, l);
        g_WThi2[nn * D + k] = h;
        g_WTlo2[nn * D + k] = l;
    }
    if (i < total4) {
        float4 v = ((const float4*)x)[i];
        __nv_bfloat16 h[4], l[4];
        split_bf16(v.x, h[0], l[0]);
        split_bf16(v.y, h[1], l[1]);
        split_bf16(v.z, h[2], l[2]);
        split_bf16(v.w, h[3], l[3]);
        *(uint2*)(g_Ahi + (size_t)i * 4) = *(uint2*)h;
        *(uint2*)(g_Alo + (size_t)i * 4) = *(uint2*)l;
    }
}

__global__ void k_deg(const int* __restrict__ cols, int e) {
    int i = blockIdx.x * blockDim.x + threadIdx.x;
    if (i < e) atomicAdd(&g_cnt[cols[i]], 1);
}

// single-block scan: g_cnt -> g_start (exclusive), g_dis, reset g_cnt, zero stats
__global__ void __launch_bounds__(1024) k_scanall(int n) {
    __shared__ int sh[1024];
    int t = threadIdx.x;
    int chunk = (n + 1023) >> 10;
    int lo = t * chunk;
    int hi = min(lo + chunk, n);
    int s = 0;
    for (int i = lo; i < hi; ++i) s += g_cnt[i];
    sh[t] = s;
    __syncthreads();
    #pragma unroll
    for (int off = 1; off < 1024; off <<= 1) {
        int v = (t >= off) ? sh[t - off] : 0;
        __syncthreads();
        sh[t] += v;
        __syncthreads();
    }
    int run = (t == 0) ? 0 : sh[t - 1];
    for (int i = lo; i < hi; ++i) {
        int c = g_cnt[i];
        g_start[i] = run;
        run += c;
        g_dis[i] = rsqrtf((float)c + 1.0f);
        g_cnt[i] = 0;
    }
    if (t < D) { g_sum[t] = 0.f; g_sumsq[t] = 0.f; }
}

__global__ void k_scatter(const int* __restrict__ rows,
                          const int* __restrict__ cols, int e) {
    int i = blockIdx.x * blockDim.x + threadIdx.x;
    if (i < e) {
        int c = cols[i];
        int p = g_start[c] + atomicAdd(&g_cnt[c], 1);
        g_srow[p] = rows[i];
    }
}

// ---------------- bf16 mma.sync GEMM with 3-term compensation ------------
#define WSTRIDE 136
#define ASTRIDE 56
#define SM_WHI 0
#define SM_WLO 34816
#define SM_AHI 69632
#define SM_ALO 83968
#define GEMM_SMEM 98304

__global__ void __launch_bounds__(256, 1)
k_gemm_mma(const __nv_bfloat16* __restrict__ Ahi,
           const __nv_bfloat16* __restrict__ Alo,
           const __nv_bfloat16* __restrict__ Whi,
           const __nv_bfloat16* __restrict__ Wlo,
           float* __restrict__ C, int n) {
    extern __shared__ __align__(16) char sm[];
    uint32_t sb = smem_u32(sm);
    int t = threadIdx.x, lane = t & 31, wid = t >> 5;
    int r0 = blockIdx.x * 128;
    int wm = (wid >> 1) * 32;
    int wn = (wid & 1) * 64;

    // stage W hi/lo [128 n][128 k]
    {
        int row = t >> 1, half = t & 1;
        const uint4* gh = (const uint4*)(Whi + row * D + half * 64);
        const uint4* gl = (const uint4*)(Wlo + row * D + half * 64);
        uint4* shh = (uint4*)(sm + SM_WHI + (row * WSTRIDE + half * 64) * 2);
        uint4* shl = (uint4*)(sm + SM_WLO + (row * WSTRIDE + half * 64) * 2);
        #pragma unroll
        for (int j = 0; j < 8; ++j) { shh[j] = gh[j]; shl[j] = gl[j]; }
    }

    int qa = lane >> 3, la = lane & 7;
    int ra = (qa & 1) * 8 + la;
    int ka = (qa >> 1) * 8;
    int nb = (qa >> 1) * 8 + la;
    int kb = (qa & 1) * 8;

    uint32_t aHiB = sb + SM_AHI + ((wm + ra) * ASTRIDE + ka) * 2;
    uint32_t aLoB = sb + SM_ALO + ((wm + ra) * ASTRIDE + ka) * 2;
    uint32_t bHiB = sb + SM_WHI + ((wn + nb) * WSTRIDE + kb) * 2;
    uint32_t bLoB = sb + SM_WLO + ((wn + nb) * WSTRIDE + kb) * 2;

    float acc[2][8][4];
    #pragma unroll
    for (int mt = 0; mt < 2; ++mt)
        #pragma unroll
        for (int nt = 0; nt < 8; ++nt)
            #pragma unroll
            for (int q = 0; q < 4; ++q) acc[mt][nt][q] = 0.f;

    int arow = t >> 1, apart = t & 1;
    int arg = r0 + arow; if (arg >= n) arg = n - 1;
    const uint4* gAh = (const uint4*)(Ahi + (size_t)arg * D + apart * 16);
    const uint4* gAl = (const uint4*)(Alo + (size_t)arg * D + apart * 16);
    uint4* sAh = (uint4*)(sm + SM_AHI + (arow * ASTRIDE + apart * 16) * 2);
    uint4* sAl = (uint4*)(sm + SM_ALO + (arow * ASTRIDE + apart * 16) * 2);

    for (int kc = 0; kc < 4; ++kc) {
        __syncthreads();
        sAh[0] = gAh[kc * 4 + 0]; sAh[1] = gAh[kc * 4 + 1];
        sAl[0] = gAl[kc * 4 + 0]; sAl[1] = gAl[kc * 4 + 1];
        __syncthreads();

        #pragma unroll
        for (int s = 0; s < 2; ++s) {
            uint32_t ah[2][4], al[2][4], bh[8][2], bl[8][2];
            #pragma unroll
            for (int mt = 0; mt < 2; ++mt) {
                uint32_t ao = (uint32_t)(mt * 16 * ASTRIDE * 2 + s * 32);
                LDSM4(ah[mt][0], ah[mt][1], ah[mt][2], ah[mt][3], aHiB + ao);
                LDSM4(al[mt][0], al[mt][1], al[mt][2], al[mt][3], aLoB + ao);
            }
            #pragma unroll
            for (int p = 0; p < 4; ++p) {
                uint32_t bo = (uint32_t)(p * 16 * WSTRIDE * 2 + (kc * 32 + s * 16) * 2);
                LDSM4(bh[2*p][0], bh[2*p][1], bh[2*p+1][0], bh[2*p+1][1], bHiB + bo);
                LDSM4(bl[2*p][0], bl[2*p][1], bl[2*p+1][0], bl[2*p+1][1], bLoB + bo);
            }
            #pragma unroll
            for (int mt = 0; mt < 2; ++mt)
                #pragma unroll
                for (int nt = 0; nt < 8; ++nt) {
                    MMA_BF16(acc[mt][nt], ah[mt], bh[nt]);
                    MMA_BF16(acc[mt][nt], al[mt], bh[nt]);
                    MMA_BF16(acc[mt][nt], ah[mt], bl[nt]);
                }
        }
    }

    int tr = lane >> 2, tc = (lane & 3) * 2;
    #pragma unroll
    for (int mt = 0; mt < 2; ++mt)
        #pragma unroll
        for (int nt = 0; nt < 8; ++nt) {
            int row = r0 + wm + mt * 16 + tr;
            int col = wn + nt * 8 + tc;
            if (row < n)
                *(float2*)(C + (size_t)row * D + col) =
                    make_float2(acc[mt][nt][0], acc[mt][nt][1]);
            if (row + 8 < n)
                *(float2*)(C + (size_t)(row + 8) * D + col) =
                    make_float2(acc[mt][nt][2], acc[mt][nt][3]);
        }
}

// -------- aggregation: warp per node, 4-way unrolled, fused epilogue -----
__global__ void __launch_bounds__(256) k_agg(const float* __restrict__ h,
                                             const float* __restrict__ b,
                                             float* __restrict__ outF,
                                             __nv_bfloat16* __restrict__ outHi,
                                             __nv_bfloat16* __restrict__ outLo,
                                             int n, int do_stats) {
    __shared__ float s_sum[D];
    __shared__ float s_sq[D];
    int tid  = threadIdx.x;
    int lane = tid & 31;
    int wid  = tid >> 5;
    if (do_stats) {
        if (tid < D) { s_sum[tid] = 0.f; s_sq[tid] = 0.f; }
        __syncthreads();
    }
    float4 b4 = *(const float4*)(b + lane * 4);

    for (int c = blockIdx.x * 8 + wid; c < n; c += gridDim.x * 8) {
        int s0  = g_start[c];
        int end = s0 + g_cnt[c];
        float4 a0 = make_float4(0.f, 0.f, 0.f, 0.f);
        float4 a1 = a0, a2 = a0, a3 = a0;
        int j = s0;
        for (; j + 4 <= end; j += 4) {
            int r0 = __ldg(&g_srow[j]);
            int r1 = __ldg(&g_srow[j + 1]);
            int r2 = __ldg(&g_srow[j + 2]);
            int r3 = __ldg(&g_srow[j + 3]);
            float d0 = __ldg(&g_dis[r0]);
            float d1 = __ldg(&g_dis[r1]);
            float d2 = __ldg(&g_dis[r2]);
            float d3 = __ldg(&g_dis[r3]);
            float4 v0 = *(const float4*)(h + (size_t)r0 * D + lane * 4);
            float4 v1 = *(const float4*)(h + (size_t)r1 * D + lane * 4);
            float4 v2 = *(const float4*)(h + (size_t)r2 * D + lane * 4);
            float4 v3 = *(const float4*)(h + (size_t)r3 * D + lane * 4);
            a0.x = fmaf(v0.x, d0, a0.x); a0.y = fmaf(v0.y, d0, a0.y);
            a0.z = fmaf(v0.z, d0, a0.z); a0.w = fmaf(v0.w, d0, a0.w);
            a1.x = fmaf(v1.x, d1, a1.x); a1.y = fmaf(v1.y, d1, a1.y);
            a1.z = fmaf(v1.z, d1, a1.z); a1.w = fmaf(v1.w, d1, a1.w);
            a2.x = fmaf(v2.x, d2, a2.x); a2.y = fmaf(v2.y, d2, a2.y);
            a2.z = fmaf(v2.z, d2, a2.z); a2.w = fmaf(v2.w, d2, a2.w);
            a3.x = fmaf(v3.x, d3, a3.x); a3.y = fmaf(v3.y, d3, a3.y);
            a3.z = fmaf(v3.z, d3, a3.z); a3.w = fmaf(v3.w, d3, a3.w);
        }
        for (; j < end; ++j) {
            int   rr = __ldg(&g_srow[j]);
            float dr = __ldg(&g_dis[rr]);
            float4 v = *(const float4*)(h + (size_t)rr * D + lane * 4);
            a0.x = fmaf(v.x, dr, a0.x); a0.y = fmaf(v.y, dr, a0.y);
            a0.z = fmaf(v.z, dr, a0.z); a0.w = fmaf(v.w, dr, a0.w);
        }
        float4 acc;
        acc.x = (a0.x + a1.x) + (a2.x + a3.x);
        acc.y = (a0.y + a1.y) + (a2.y + a3.y);
        acc.z = (a0.z + a1.z) + (a2.z + a3.z);
        acc.w = (a0.w + a1.w) + (a2.w + a3.w);

        float dc = g_dis[c];
        float sc = dc * dc;
        float4 hc = *(const float4*)(h + (size_t)c * D + lane * 4);
        float4 r4;
        r4.x = fmaxf(fmaf(acc.x, dc, fmaf(hc.x, sc, b4.x)), 0.f);
        r4.y = fmaxf(fmaf(acc.y, dc, fmaf(hc.y, sc, b4.y)), 0.f);
        r4.z = fmaxf(fmaf(acc.z, dc, fmaf(hc.z, sc, b4.z)), 0.f);
        r4.w = fmaxf(fmaf(acc.w, dc, fmaf(hc.w, sc, b4.w)), 0.f);
        if (do_stats) {
            *(float4*)(outF + (size_t)c * D + lane * 4) = r4;
            int d0 = lane * 4;
            atomicAdd(&s_sum[d0 + 0], r4.x); atomicAdd(&s_sq[d0 + 0], r4.x * r4.x);
            atomicAdd(&s_sum[d0 + 1], r4.y); atomicAdd(&s_sq[d0 + 1], r4.y * r4.y);
            atomicAdd(&s_sum[d0 + 2], r4.z); atomicAdd(&s_sq[d0 + 2], r4.z * r4.z);
            atomicAdd(&s_sum[d0 + 3], r4.w); atomicAdd(&s_sq[d0 + 3], r4.w * r4.w);
        } else {
            __nv_bfloat16 hh[4], ll[4];
            split_bf16(r4.x, hh[0], ll[0]);
            split_bf16(r4.y, hh[1], ll[1]);
            split_bf16(r4.z, hh[2], ll[2]);
            split_bf16(r4.w, hh[3], ll[3]);
            *(uint2*)(outHi + (size_t)c * D + lane * 4) = *(uint2*)hh;
            *(uint2*)(outLo + (size_t)c * D + lane * 4) = *(uint2*)ll;
        }
    }
    if (do_stats) {
        __syncthreads();
        if (tid < D) {
            atomicAdd(&g_sum[tid], s_sum[tid]);
            atomicAdd(&g_sumsq[tid], s_sq[tid]);
        }
    }
}

// ---------------- BatchNorm apply ----------------
__global__ void k_bn(const float* __restrict__ h,
                     const float* __restrict__ gamma,
                     const float* __restrict__ beta,
                     float* __restrict__ out, int n) {
    int idx = blockIdx.x * blockDim.x + threadIdx.x;
    int total = n * (D / 4);
    if (idx >= total) return;
    int d0 = (idx & 31) * 4;
    float invN = 1.0f / (float)n;
    float4 v = ((const float4*)h)[idx];
    float vv[4] = {v.x, v.y, v.z, v.w};
    float res[4];
    #pragma unroll
    for (int s = 0; s < 4; ++s) {
        int d = d0 + s;
        float m   = g_sum[d] * invN;
        float var = g_sumsq[d] * invN - m * m;
        float inv = rsqrtf(var + EPSV);
        res[s] = gamma[d] * (vv[s] - m) * inv + beta[d];
    }
    ((float4*)out)[idx] = make_float4(res[0], res[1], res[2], res[3]);
}

// ---------------- launch ----------------
extern "C" void kernel_launch(void* const* d_in, const int* in_sizes, int n_in,
                              void* d_out, int out_size) {
    const float* x     = (const float*)d_in[0];
    const int*   ei    = (const int*)d_in[1];
    const float* W1    = (const float*)d_in[2];
    const float* b1    = (const float*)d_in[3];
    const float* W2    = (const float*)d_in[4];
    const float* b2    = (const float*)d_in[5];
    const float* gamma = (const float*)d_in[6];
    const float* beta  = (const float*)d_in[7];
    float* out = (float*)d_out;

    int n = in_sizes[0] / D;
    int e = in_sizes[1] / 2;
    const int* rows = ei;
    const int* cols = ei + e;
    int total4 = n * (D / 4);

    float *bufH, *bufB;
    __nv_bfloat16 *ahi, *alo, *wh1, *wl1, *wh2, *wl2;
    cudaGetSymbolAddress((void**)&bufH, g_bufH);
    cudaGetSymbolAddress((void**)&bufB, g_bufB);
    cudaGetSymbolAddress((void**)&ahi, g_Ahi);
    cudaGetSymbolAddress((void**)&alo, g_Alo);
    cudaGetSymbolAddress((void**)&wh1, g_WThi1);
    cudaGetSymbolAddress((void**)&wl1, g_WTlo1);
    cudaGetSymbolAddress((void**)&wh2, g_WThi2);
    cudaGetSymbolAddress((void**)&wl2, g_WTlo2);

    cudaFuncSetAttribute(k_gemm_mma, cudaFuncAttributeMaxDynamicSharedMemorySize,
                         GEMM_SMEM);

    int tb = 256;
    int nb_e    = (e + tb - 1) / tb;
    int nb_f4   = (total4 + tb - 1) / tb;
    int nb_prep = (total4 + tb - 1) / tb;        // total4 > max(n, D*D)
    int gemm_grid = (n + 127) / 128;
    int agg_grid = 2048;

    // 1: merged prep (zero cnt + split W1/W2/x)
    k_prep<<<nb_prep, tb>>>(W1, W2, x, n, total4);
    // 2: degree histogram
    k_deg<<<nb_e, tb>>>(cols, e);
    // 3: scan + dis
    k_scanall<<<1, 1024>>>(n);
    // 4: layer-1 GEMM  (<-- profiler capture slot)
    k_gemm_mma<<<gemm_grid, 256, GEMM_SMEM>>>(ahi, alo, wh1, wl1, bufH, n);
    // 5: CSR scatter
    k_scatter<<<nb_e, tb>>>(rows, cols, e);
    // 6: layer-1 aggregation -> bf16 hi/lo
    k_agg<<<agg_grid, 256>>>(bufH, b1, nullptr, ahi, alo, n, 0);
    // 7: layer-2 GEMM
    k_gemm_mma<<<gemm_grid, 256, GEMM_SMEM>>>(ahi, alo, wh2, wl2, bufH, n);
    // 8: layer-2 aggregation -> float + stats
    k_agg<<<agg_grid, 256>>>(bufH, b2, bufB, nullptr, nullptr, n, 1);
    // 9: batchnorm
    k_bn<<<nb_f4, tb>>>(bufB, gamma, beta, out, n);
}